// round 11
// baseline (speedup 1.0000x reference)
#include <cuda_runtime.h>
#include <cuda_fp16.h>
#include <math.h>
#include <mma.h>
#include <stdint.h>

using namespace nvcuda;

#define BB 32
#define TT 1024
#define DD 512
#define MM (BB * TT)

// Scratch (__device__ globals; no allocations allowed)
__device__ float  g_brep[16 * DD];
__device__ __half g_Kh[MM * DD];
__device__ __half g_Vh[MM * DD];
__device__ __half g_Qh[MM * DD];
__device__ __half g_xh[MM * DD];
__device__ __half g_W3h[3 * DD * DD];
__device__ __half g_Woh[DD * DD];
__device__ __half g_expwh[TT * TT];
__device__ __half g_EKh[MM * DD];
__device__ __half g_EKVh[MM * DD];
__device__ __half g_Yth[MM * DD];

__device__ __forceinline__ uint32_t smem_u32(const void* p) {
    uint32_t a;
    asm("{ .reg .u64 t; cvta.to.shared.u64 t, %1; cvt.u32.u64 %0, t; }"
        : "=r"(a) : "l"(p));
    return a;
}

#define CP16(dst, src) \
    asm volatile("cp.async.cg.shared.global [%0], [%1], 16;" \
        :: "r"(smem_u32(dst)), "l"((const void*)(src)) : "memory")
#define CP_COMMIT() asm volatile("cp.async.commit_group;" ::: "memory")
#define CP_WAIT0()  asm volatile("cp.async.wait_group 0;" ::: "memory")
#define CP_WAIT1()  asm volatile("cp.async.wait_group 1;" ::: "memory")

// ===========================================================================
// Linear NT GEMM (fp16 WMMA, fp32 acc, 3-stage cp.async, 2 in flight)
// Block 128x128, 256 threads, 8 warps (2x4), warp tile 64x32. K-chunk 32.
// 2 CTAs/SM (smem 61440 B, regs <= 128) => 16 warps/SM.
// Fused mode (outf==null): convert acc to half, route to Kh/Vh/Qh by n>>9.
// ===========================================================================
#define L_STAGE 10240   // halves per stage: As 128*40 + Bs 128*40
#define L_NST 3
#define L_SMEM (L_NST * L_STAGE * 2)   // 61440 B

__global__ __launch_bounds__(256, 2)
void linh(const __half* __restrict__ A, const __half* __restrict__ W,
          const float* __restrict__ brep,
          __half* __restrict__ Kh, __half* __restrict__ Vh, __half* __restrict__ Qh,
          float* __restrict__ outf)
{
    extern __shared__ __half sh[];
    const int tid = threadIdx.x;
    const int wid = tid >> 5;
    const int wm = wid >> 2;          // 0..1 (64 rows)
    const int wn = wid & 3;           // 0..3 (32 cols)
    const int m0 = blockIdx.y * 128, n0 = blockIdx.x * 128;

    wmma::fragment<wmma::accumulator, 16, 16, 16, float> c[4][2];
#pragma unroll
    for (int i = 0; i < 4; i++)
#pragma unroll
        for (int j = 0; j < 2; j++) {
            if (outf)
                wmma::load_matrix_sync(c[i][j],
                    brep + ((n0 + wn * 32 + j * 16) & (DD - 1)),
                    DD, wmma::mem_row_major);
            else
                wmma::fill_fragment(c[i][j], 0.0f);
        }

    auto issue = [&](int chunk) {
        __half* As = sh + (chunk % L_NST) * L_STAGE;
        __half* Bs = As + 128 * 40;
        const int k0 = chunk * 32;
#pragma unroll
        for (int i = 0; i < 2; i++) {
            const int f = tid + i * 256;
            const int row = f >> 2, c8 = f & 3;
            CP16(As + row * 40 + c8 * 8, A + (size_t)(m0 + row) * DD + k0 + c8 * 8);
        }
#pragma unroll
        for (int i = 0; i < 2; i++) {
            const int f = tid + i * 256;
            const int row = f >> 2, c8 = f & 3;
            CP16(Bs + row * 40 + c8 * 8, W + (size_t)(n0 + row) * DD + k0 + c8 * 8);
        }
        CP_COMMIT();
    };

    issue(0); issue(1);

    const int NC = DD / 32;   // 16
    for (int ch = 0; ch < NC; ch++) {
        if (ch <= NC - 2) CP_WAIT1();
        else              CP_WAIT0();
        __syncthreads();
        if (ch + 2 < NC) issue(ch + 2);

        const __half* As = sh + (ch % L_NST) * L_STAGE;
        const __half* Bs = As + 128 * 40;
#pragma unroll
        for (int kk = 0; kk < 2; kk++) {
            wmma::fragment<wmma::matrix_a, 16, 16, 16, __half, wmma::row_major> a[4];
            wmma::fragment<wmma::matrix_b, 16, 16, 16, __half, wmma::col_major> b[2];
#pragma unroll
            for (int i = 0; i < 4; i++)
                wmma::load_matrix_sync(a[i], As + (wm * 64 + i * 16) * 40 + kk * 16, 40);
#pragma unroll
            for (int j = 0; j < 2; j++)
                wmma::load_matrix_sync(b[j], Bs + (wn * 32 + j * 16) * 40 + kk * 16, 40);
#pragma unroll
            for (int i = 0; i < 4; i++)
#pragma unroll
                for (int j = 0; j < 2; j++)
                    wmma::mma_sync(c[i][j], a[i], b[j], c[i][j]);
        }
    }

    if (outf) {
#pragma unroll
        for (int i = 0; i < 4; i++)
#pragma unroll
            for (int j = 0; j < 2; j++)
                wmma::store_matrix_sync(outf + (size_t)(m0 + wm * 64 + i * 16) * DD
                                             + n0 + wn * 32 + j * 16,
                                        c[i][j], DD, wmma::mem_row_major);
    } else {
        const int mat = n0 >> 9;
        __half* dst = (mat == 0) ? Kh : (mat == 1) ? Vh : Qh;
        const int col0 = n0 & 511;
        wmma::fragment<wmma::accumulator, 16, 16, 16, __half> chf;
#pragma unroll
        for (int i = 0; i < 4; i++)
#pragma unroll
            for (int j = 0; j < 2; j++) {
#pragma unroll
                for (int e = 0; e < chf.num_elements; e++)
                    chf.x[e] = __float2half(c[i][j].x[e]);
                wmma::store_matrix_sync(dst + (size_t)(m0 + wm * 64 + i * 16) * DD
                                            + col0 + wn * 32 + j * 16,
                                        chf, DD, wmma::mem_row_major);
            }
    }
}

// ===========================================================================
// Attention (fp16 WMMA): num = expw @ EKV, den = expw @ EK per batch.
// Division in registers; only ratio staged in smem.
// Block 128(t) x 64(d), 128 threads, 4 warps (2x2), warp 64x32 dual-acc.
// 3-stage cp.async, 2 in flight, 3 CTAs/SM.  (unchanged control)
// ===========================================================================
#define A_STAGE 9728    // halves: Ws 128*40 + EK 32*72 + EKV 32*72
#define A_NST 3
#define A_SMEM (A_NST * A_STAGE * 2)   // 58368 B

__global__ __launch_bounds__(128, 3)
void attnh(const __half* __restrict__ expw, const __half* __restrict__ EK,
           const __half* __restrict__ EKV, const __half* __restrict__ Qh,
           const float* __restrict__ bq, __half* __restrict__ Yt)
{
    extern __shared__ __half sh[];
    const int tid = threadIdx.x;
    const int wid = tid >> 5;
    const int wm = wid >> 1;          // 0..1 (64 t-rows)
    const int wn = wid & 1;           // 0..1 (32 d-cols)
    const int d0 = blockIdx.x * 64, t0 = blockIdx.y * 128, b = blockIdx.z;

    const __half* ekb  = EK  + (size_t)b * TT * DD;
    const __half* ekvb = EKV + (size_t)b * TT * DD;

    wmma::fragment<wmma::accumulator, 16, 16, 16, float> cN[4][2], cD[4][2];
#pragma unroll
    for (int i = 0; i < 4; i++)
#pragma unroll
        for (int j = 0; j < 2; j++) {
            wmma::fill_fragment(cN[i][j], 0.0f);
            wmma::fill_fragment(cD[i][j], 0.0f);
        }

    auto issue = [&](int chunk) {
        __half* Ws  = sh + (chunk % A_NST) * A_STAGE;
        __half* EKs = Ws + 128 * 40;
        __half* EVs = EKs + 32 * 72;
        const int s0 = chunk * 32;
#pragma unroll
        for (int i = 0; i < 4; i++) {
            const int f = tid + i * 128;
            const int row = f >> 2, c8 = f & 3;
            CP16(Ws + row * 40 + c8 * 8, expw + (size_t)(t0 + row) * TT + s0 + c8 * 8);
        }
#pragma unroll
        for (int i = 0; i < 2; i++) {
            const int f = tid + i * 128;
            const int row = f >> 3, c8 = f & 7;
            CP16(EKs + row * 72 + c8 * 8, ekb  + (size_t)(s0 + row) * DD + d0 + c8 * 8);
            CP16(EVs + row * 72 + c8 * 8, ekvb + (size_t)(s0 + row) * DD + d0 + c8 * 8);
        }
        CP_COMMIT();
    };

    issue(0); issue(1);

    const int NC = TT / 32;   // 32
    for (int ch = 0; ch < NC; ch++) {
        if (ch <= NC - 2) CP_WAIT1();
        else              CP_WAIT0();
        __syncthreads();
        if (ch + 2 < NC) issue(ch + 2);

        const __half* Ws  = sh + (ch % A_NST) * A_STAGE;
        const __half* EKs = Ws + 128 * 40;
        const __half* EVs = EKs + 32 * 72;
#pragma unroll
        for (int kk = 0; kk < 2; kk++) {
            wmma::fragment<wmma::matrix_a, 16, 16, 16, __half, wmma::row_major> a[4];
            wmma::fragment<wmma::matrix_b, 16, 16, 16, __half, wmma::row_major> bK[2], bV[2];
#pragma unroll
            for (int i = 0; i < 4; i++)
                wmma::load_matrix_sync(a[i], Ws + (wm * 64 + i * 16) * 40 + kk * 16, 40);
#pragma unroll
            for (int j = 0; j < 2; j++) {
                wmma::load_matrix_sync(bK[j], EKs + (kk * 16) * 72 + wn * 32 + j * 16, 72);
                wmma::load_matrix_sync(bV[j], EVs + (kk * 16) * 72 + wn * 32 + j * 16, 72);
            }
#pragma unroll
            for (int i = 0; i < 4; i++)
#pragma unroll
                for (int j = 0; j < 2; j++) {
                    wmma::mma_sync(cN[i][j], a[i], bV[j], cN[i][j]);
                    wmma::mma_sync(cD[i][j], a[i], bK[j], cD[i][j]);
                }
        }
    }

    __syncthreads();
    float* ratio = (float*)sh;           // [128][68]
#pragma unroll
    for (int i = 0; i < 4; i++)
#pragma unroll
        for (int j = 0; j < 2; j++) {
#pragma unroll
            for (int e = 0; e < cN[i][j].num_elements; e++)
                cN[i][j].x[e] /= cD[i][j].x[e];
            wmma::store_matrix_sync(&ratio[(wm * 64 + i * 16) * 68 + wn * 32 + j * 16],
                                    cN[i][j], 68, wmma::mem_row_major);
        }
    __syncthreads();

#pragma unroll
    for (int it = 0; it < 16; it++) {
        const int f = tid + it * 128;        // 0..2047 groups of 4 over 128x64
        const int row = f >> 4, c4 = f & 15;
        const size_t qidx = ((size_t)b * TT + t0 + row) * DD + d0 + c4 * 4;
        const __half2* qp = (const __half2*)(Qh + qidx);
        float2 q01 = __half22float2(qp[0]);
        float2 q23 = __half22float2(qp[1]);
        float4 b4 = __ldg((const float4*)(bq + d0 + c4 * 4));
        const float* rp = &ratio[row * 68 + c4 * 4];
        float ox = (1.f / (1.f + expf(-(q01.x + b4.x)))) * rp[0];
        float oy = (1.f / (1.f + expf(-(q01.y + b4.y)))) * rp[1];
        float oz = (1.f / (1.f + expf(-(q23.x + b4.z)))) * rp[2];
        float ow = (1.f / (1.f + expf(-(q23.y + b4.w)))) * rp[3];
        __half2* yp = (__half2*)(Yt + qidx);
        yp[0] = __floats2half2_rn(ox, oy);
        yp[1] = __floats2half2_rn(oz, ow);
    }
}

// ===========================================================================
// Elementwise / conversion kernels
// ===========================================================================
__global__ __launch_bounds__(256)
void expw_kernel(const float* __restrict__ w, __half* __restrict__ ew)
{
    const int t = blockIdx.x;
    const float* row = w + (size_t)t * TT;
    float m = -INFINITY;
    for (int i = threadIdx.x; i < TT; i += 256) m = fmaxf(m, row[i]);
#pragma unroll
    for (int o = 16; o > 0; o >>= 1) m = fmaxf(m, __shfl_xor_sync(0xffffffffu, m, o));
    __shared__ float warpmax[8];
    __shared__ float rowmax;
    if ((threadIdx.x & 31) == 0) warpmax[threadIdx.x >> 5] = m;
    __syncthreads();
    if (threadIdx.x == 0) {
        float mm = warpmax[0];
#pragma unroll
        for (int i = 1; i < 8; i++) mm = fmaxf(mm, warpmax[i]);
        rowmax = mm;
    }
    __syncthreads();
    const float rm = rowmax;
    for (int i = threadIdx.x; i < TT; i += 256)
        ew[(size_t)t * TT + i] = __float2half(expf(row[i] - rm));
}

// Fused batch-max + exp + bias-fold over half K/V (half2 lanes)
__global__ __launch_bounds__(256)
void kmax_ekv_kernel(const __half* __restrict__ Kh, const __half* __restrict__ Vh,
                     const float* __restrict__ bv,
                     __half* __restrict__ EK, __half* __restrict__ EKV)
{
    const int idx = (blockIdx.x * 256 + threadIdx.x) * 2;   // < TT*DD
    const float bv0 = bv[idx & (DD - 1)];
    const float bv1 = bv[(idx + 1) & (DD - 1)];
    float2 kv[BB];
    float m0 = -INFINITY, m1 = -INFINITY;
#pragma unroll
    for (int b = 0; b < BB; b++) {
        kv[b] = __half22float2(*(const __half2*)(Kh + (size_t)b * TT * DD + idx));
        m0 = fmaxf(m0, kv[b].x);
        m1 = fmaxf(m1, kv[b].y);
    }
#pragma unroll
    for (int b = 0; b < BB; b++) {
        const size_t gi = (size_t)b * TT * DD + idx;
        float2 v = __half22float2(*(const __half2*)(Vh + gi));
        const float e0 = expf(kv[b].x - m0);
        const float e1 = expf(kv[b].y - m1);
        *(__half2*)(EK + gi)  = __floats2half2_rn(e0, e1);
        *(__half2*)(EKV + gi) = __floats2half2_rn(e0 * (v.x + bv0), e1 * (v.y + bv1));
    }
}

// Merged prep: f2h(x) [blocks 0..16383], wconv [16384..17407], brep [17408..17439]
__global__ __launch_bounds__(256)
void prep_kernel(const float* __restrict__ x, __half* __restrict__ xh,
                 const float* __restrict__ Wk, const float* __restrict__ Wv,
                 const float* __restrict__ Wq, const float* __restrict__ Wo,
                 __half* __restrict__ W3h, __half* __restrict__ Woh,
                 const float* __restrict__ bo, float* __restrict__ brep)
{
    const int blk = blockIdx.x;
    if (blk < 16384) {
        const size_t f = (size_t)blk * 256 + threadIdx.x;   // f4 index over x
        float4 v = ((const float4*)x)[f];
        __half2* d = (__half2*)(xh + f * 4);
        d[0] = __floats2half2_rn(v.x, v.y);
        d[1] = __floats2half2_rn(v.z, v.w);
    } else if (blk < 17408) {
        const int f = (blk - 16384) * 256 + threadIdx.x;    // f4 index < 4*65536
        const int per = DD * DD / 4;
        const float* src; __half* dst; int off;
        if (f < per)           { src = Wk; dst = W3h;            off = f; }
        else if (f < 2 * per)  { src = Wv; dst = W3h + DD * DD;  off = f - per; }
        else if (f < 3 * per)  { src = Wq; dst = W3h + 2*DD*DD;  off = f - 2 * per; }
        else                   { src = Wo; dst = Woh;            off = f - 3 * per; }
        float4 v = ((const float4*)src)[off];
        __half2* d = (__half2*)(dst + (size_t)off * 4);
        d[0] = __floats2half2_rn(v.x, v.y);
        d[1] = __floats2half2_rn(v.z, v.w);
    } else {
        const int idx = (blk - 17408) * 256 + threadIdx.x;  // < 16*DD
        brep[idx] = bo[idx & (DD - 1)];
    }
}

// ===========================================================================
extern "C" void kernel_launch(void* const* d_in, const int* in_sizes, int n_in,
                              void* d_out, int out_size)
{
    const float* x    = (const float*)d_in[0];
    const float* Wk_w = (const float*)d_in[1];
    // Wk_b unused: K bias cancels inside exp(K - max_b K)
    const float* Wv_w = (const float*)d_in[3];
    const float* Wv_b = (const float*)d_in[4];
    const float* Wq_w = (const float*)d_in[5];
    const float* Wq_b = (const float*)d_in[6];
    const float* w    = (const float*)d_in[7];
    const float* Wo_w = (const float*)d_in[8];
    const float* Wo_b = (const float*)d_in[9];
    float* out = (float*)d_out;

    float *pbrep;
    __half *pKh, *pVh, *pQh, *pxh, *pW3h, *pWoh, *pexpwh, *pEKh, *pEKVh, *pYth;
    cudaGetSymbolAddress((void**)&pbrep, g_brep);
    cudaGetSymbolAddress((void**)&pKh, g_Kh);
    cudaGetSymbolAddress((void**)&pVh, g_Vh);
    cudaGetSymbolAddress((void**)&pQh, g_Qh);
    cudaGetSymbolAddress((void**)&pxh, g_xh);
    cudaGetSymbolAddress((void**)&pW3h, g_W3h);
    cudaGetSymbolAddress((void**)&pWoh, g_Woh);
    cudaGetSymbolAddress((void**)&pexpwh, g_expwh);
    cudaGetSymbolAddress((void**)&pEKh, g_EKh);
    cudaGetSymbolAddress((void**)&pEKVh, g_EKVh);
    cudaGetSymbolAddress((void**)&pYth, g_Yth);

    cudaFuncSetAttribute(linh,  cudaFuncAttributeMaxDynamicSharedMemorySize, L_SMEM);
    cudaFuncSetAttribute(attnh, cudaFuncAttributeMaxDynamicSharedMemorySize, A_SMEM);

    // Prep (launch #1-2); #3 = fused KVQ GEMM lands in the ncu capture window
    prep_kernel<<<17440, 256>>>(x, pxh, Wk_w, Wv_w, Wq_w, Wo_w, pW3h, pWoh, Wo_b, pbrep);
    expw_kernel<<<TT, 256>>>(w, pexpwh);

    // Fused K/V/Q linear (half out): N = 1536 -> grid (12, 256)
    linh<<<dim3(12, MM / 128), 256, L_SMEM>>>(pxh, pW3h, pbrep, pKh, pVh, pQh, nullptr);

    kmax_ekv_kernel<<<(TT * DD / 2) / 256, 256>>>(pKh, pVh, Wv_b, pEKh, pEKVh);

    attnh<<<dim3(DD / 64, TT / 128, BB), 128, A_SMEM>>>(pexpwh, pEKh, pEKVh, pQh, Wq_b, pYth);

    // Final linear with bias (fp32 out): N = 512 -> grid (4, 256)
    linh<<<dim3(4, MM / 128), 256, L_SMEM>>>(pYth, pWoh, pbrep, nullptr, nullptr, nullptr, out);
}

// round 12
// speedup vs baseline: 1.0237x; 1.0237x over previous
#include <cuda_runtime.h>
#include <cuda_fp16.h>
#include <math.h>
#include <mma.h>
#include <stdint.h>

using namespace nvcuda;

#define BB 32
#define TT 1024
#define DD 512
#define MM (BB * TT)

// Scratch (__device__ globals; no allocations allowed)
__device__ float  g_brep[16 * DD];
__device__ __half g_Kh[MM * DD];
__device__ __half g_Vh[MM * DD];
__device__ __half g_Qh[MM * DD];
__device__ __half g_xh[MM * DD];
__device__ __half g_W3h[3 * DD * DD];
__device__ __half g_Woh[DD * DD];
__device__ __half g_expwh[TT * TT];
__device__ __half g_EKh[MM * DD];
__device__ __half g_EKVh[MM * DD];
__device__ __half g_Yth[MM * DD];

__device__ __forceinline__ uint32_t smem_u32(const void* p) {
    uint32_t a;
    asm("{ .reg .u64 t; cvta.to.shared.u64 t, %1; cvt.u32.u64 %0, t; }"
        : "=r"(a) : "l"(p));
    return a;
}

#define CP16(dst, src) \
    asm volatile("cp.async.cg.shared.global [%0], [%1], 16;" \
        :: "r"(smem_u32(dst)), "l"((const void*)(src)) : "memory")
#define CP_COMMIT() asm volatile("cp.async.commit_group;" ::: "memory")
#define CP_WAIT0()  asm volatile("cp.async.wait_group 0;" ::: "memory")
#define CP_WAIT1()  asm volatile("cp.async.wait_group 1;" ::: "memory")

// ===========================================================================
// Linear NT GEMM (fp16 WMMA, fp32 acc, 3-stage cp.async, 2 in flight)
// Block 128x128, 128 threads, 4 warps (2x2), warp tile 64x64. K-chunk 32.
// 3 CTAs/SM => 12 warps/SM (reverted to the R10 proven config).
// Fused mode (outf==null): convert acc to half, route to Kh/Vh/Qh by n>>9.
// ===========================================================================
#define L_STAGE 10240   // halves per stage: As 128*40 + Bs 128*40
#define L_NST 3
#define L_SMEM (L_NST * L_STAGE * 2)   // 61440 B

__global__ __launch_bounds__(128, 3)
void linh(const __half* __restrict__ A, const __half* __restrict__ W,
          const float* __restrict__ brep,
          __half* __restrict__ Kh, __half* __restrict__ Vh, __half* __restrict__ Qh,
          float* __restrict__ outf)
{
    extern __shared__ __half sh[];
    const int tid = threadIdx.x;
    const int wid = tid >> 5;
    const int wm = wid >> 1;          // 0..1 (64 rows)
    const int wn = wid & 1;           // 0..1 (64 cols)
    const int m0 = blockIdx.y * 128, n0 = blockIdx.x * 128;

    wmma::fragment<wmma::accumulator, 16, 16, 16, float> c[4][4];
#pragma unroll
    for (int i = 0; i < 4; i++)
#pragma unroll
        for (int j = 0; j < 4; j++) {
            if (outf)
                wmma::load_matrix_sync(c[i][j],
                    brep + ((n0 + wn * 64 + j * 16) & (DD - 1)),
                    DD, wmma::mem_row_major);
            else
                wmma::fill_fragment(c[i][j], 0.0f);
        }

    auto issue = [&](int chunk) {
        __half* As = sh + (chunk % L_NST) * L_STAGE;
        __half* Bs = As + 128 * 40;
        const int k0 = chunk * 32;
#pragma unroll
        for (int i = 0; i < 4; i++) {
            const int f = tid + i * 128;
            const int row = f >> 2, c8 = f & 3;
            CP16(As + row * 40 + c8 * 8, A + (size_t)(m0 + row) * DD + k0 + c8 * 8);
        }
#pragma unroll
        for (int i = 0; i < 4; i++) {
            const int f = tid + i * 128;
            const int row = f >> 2, c8 = f & 3;
            CP16(Bs + row * 40 + c8 * 8, W + (size_t)(n0 + row) * DD + k0 + c8 * 8);
        }
        CP_COMMIT();
    };

    issue(0); issue(1);

    const int NC = DD / 32;   // 16
    for (int ch = 0; ch < NC; ch++) {
        if (ch <= NC - 2) CP_WAIT1();
        else              CP_WAIT0();
        __syncthreads();
        if (ch + 2 < NC) issue(ch + 2);

        const __half* As = sh + (ch % L_NST) * L_STAGE;
        const __half* Bs = As + 128 * 40;
#pragma unroll
        for (int kk = 0; kk < 2; kk++) {
            wmma::fragment<wmma::matrix_a, 16, 16, 16, __half, wmma::row_major> a[4];
            wmma::fragment<wmma::matrix_b, 16, 16, 16, __half, wmma::col_major> b[4];
#pragma unroll
            for (int i = 0; i < 4; i++)
                wmma::load_matrix_sync(a[i], As + (wm * 64 + i * 16) * 40 + kk * 16, 40);
#pragma unroll
            for (int j = 0; j < 4; j++)
                wmma::load_matrix_sync(b[j], Bs + (wn * 64 + j * 16) * 40 + kk * 16, 40);
#pragma unroll
            for (int i = 0; i < 4; i++)
#pragma unroll
                for (int j = 0; j < 4; j++)
                    wmma::mma_sync(c[i][j], a[i], b[j], c[i][j]);
        }
    }

    if (outf) {
#pragma unroll
        for (int i = 0; i < 4; i++)
#pragma unroll
            for (int j = 0; j < 4; j++)
                wmma::store_matrix_sync(outf + (size_t)(m0 + wm * 64 + i * 16) * DD
                                             + n0 + wn * 64 + j * 16,
                                        c[i][j], DD, wmma::mem_row_major);
    } else {
        const int mat = n0 >> 9;
        __half* dst = (mat == 0) ? Kh : (mat == 1) ? Vh : Qh;
        const int col0 = n0 & 511;
        wmma::fragment<wmma::accumulator, 16, 16, 16, __half> chf;
#pragma unroll
        for (int i = 0; i < 4; i++)
#pragma unroll
            for (int j = 0; j < 4; j++) {
#pragma unroll
                for (int e = 0; e < chf.num_elements; e++)
                    chf.x[e] = __float2half(c[i][j].x[e]);
                wmma::store_matrix_sync(dst + (size_t)(m0 + wm * 64 + i * 16) * DD
                                            + col0 + wn * 64 + j * 16,
                                        chf, DD, wmma::mem_row_major);
            }
    }
}

// ===========================================================================
// Attention (fp16 WMMA): num = expw @ EKV, den = expw @ EK per batch.
// Division in registers; only ratio staged in smem.
// Block 128(t) x 64(d), 128 threads, 4 warps (2x2), warp 64x32 dual-acc.
// 3-stage cp.async, 2 in flight, 3 CTAs/SM. (unchanged control)
// ===========================================================================
#define A_STAGE 9728    // halves: Ws 128*40 + EK 32*72 + EKV 32*72
#define A_NST 3
#define A_SMEM (A_NST * A_STAGE * 2)   // 58368 B

__global__ __launch_bounds__(128, 3)
void attnh(const __half* __restrict__ expw, const __half* __restrict__ EK,
           const __half* __restrict__ EKV, const __half* __restrict__ Qh,
           const float* __restrict__ bq, __half* __restrict__ Yt)
{
    extern __shared__ __half sh[];
    const int tid = threadIdx.x;
    const int wid = tid >> 5;
    const int wm = wid >> 1;          // 0..1 (64 t-rows)
    const int wn = wid & 1;           // 0..1 (32 d-cols)
    const int d0 = blockIdx.x * 64, t0 = blockIdx.y * 128, b = blockIdx.z;

    const __half* ekb  = EK  + (size_t)b * TT * DD;
    const __half* ekvb = EKV + (size_t)b * TT * DD;

    wmma::fragment<wmma::accumulator, 16, 16, 16, float> cN[4][2], cD[4][2];
#pragma unroll
    for (int i = 0; i < 4; i++)
#pragma unroll
        for (int j = 0; j < 2; j++) {
            wmma::fill_fragment(cN[i][j], 0.0f);
            wmma::fill_fragment(cD[i][j], 0.0f);
        }

    auto issue = [&](int chunk) {
        __half* Ws  = sh + (chunk % A_NST) * A_STAGE;
        __half* EKs = Ws + 128 * 40;
        __half* EVs = EKs + 32 * 72;
        const int s0 = chunk * 32;
#pragma unroll
        for (int i = 0; i < 4; i++) {
            const int f = tid + i * 128;
            const int row = f >> 2, c8 = f & 3;
            CP16(Ws + row * 40 + c8 * 8, expw + (size_t)(t0 + row) * TT + s0 + c8 * 8);
        }
#pragma unroll
        for (int i = 0; i < 2; i++) {
            const int f = tid + i * 128;
            const int row = f >> 3, c8 = f & 7;
            CP16(EKs + row * 72 + c8 * 8, ekb  + (size_t)(s0 + row) * DD + d0 + c8 * 8);
            CP16(EVs + row * 72 + c8 * 8, ekvb + (size_t)(s0 + row) * DD + d0 + c8 * 8);
        }
        CP_COMMIT();
    };

    issue(0); issue(1);

    const int NC = TT / 32;   // 32
    for (int ch = 0; ch < NC; ch++) {
        if (ch <= NC - 2) CP_WAIT1();
        else              CP_WAIT0();
        __syncthreads();
        if (ch + 2 < NC) issue(ch + 2);

        const __half* Ws  = sh + (ch % A_NST) * A_STAGE;
        const __half* EKs = Ws + 128 * 40;
        const __half* EVs = EKs + 32 * 72;
#pragma unroll
        for (int kk = 0; kk < 2; kk++) {
            wmma::fragment<wmma::matrix_a, 16, 16, 16, __half, wmma::row_major> a[4];
            wmma::fragment<wmma::matrix_b, 16, 16, 16, __half, wmma::row_major> bK[2], bV[2];
#pragma unroll
            for (int i = 0; i < 4; i++)
                wmma::load_matrix_sync(a[i], Ws + (wm * 64 + i * 16) * 40 + kk * 16, 40);
#pragma unroll
            for (int j = 0; j < 2; j++) {
                wmma::load_matrix_sync(bK[j], EKs + (kk * 16) * 72 + wn * 32 + j * 16, 72);
                wmma::load_matrix_sync(bV[j], EVs + (kk * 16) * 72 + wn * 32 + j * 16, 72);
            }
#pragma unroll
            for (int i = 0; i < 4; i++)
#pragma unroll
                for (int j = 0; j < 2; j++) {
                    wmma::mma_sync(cN[i][j], a[i], bV[j], cN[i][j]);
                    wmma::mma_sync(cD[i][j], a[i], bK[j], cD[i][j]);
                }
        }
    }

    __syncthreads();
    float* ratio = (float*)sh;           // [128][68]
#pragma unroll
    for (int i = 0; i < 4; i++)
#pragma unroll
        for (int j = 0; j < 2; j++) {
#pragma unroll
            for (int e = 0; e < cN[i][j].num_elements; e++)
                cN[i][j].x[e] /= cD[i][j].x[e];
            wmma::store_matrix_sync(&ratio[(wm * 64 + i * 16) * 68 + wn * 32 + j * 16],
                                    cN[i][j], 68, wmma::mem_row_major);
        }
    __syncthreads();

#pragma unroll
    for (int it = 0; it < 16; it++) {
        const int f = tid + it * 128;        // 0..2047 groups of 4 over 128x64
        const int row = f >> 4, c4 = f & 15;
        const size_t qidx = ((size_t)b * TT + t0 + row) * DD + d0 + c4 * 4;
        const __half2* qp = (const __half2*)(Qh + qidx);
        float2 q01 = __half22float2(qp[0]);
        float2 q23 = __half22float2(qp[1]);
        float4 b4 = __ldg((const float4*)(bq + d0 + c4 * 4));
        const float* rp = &ratio[row * 68 + c4 * 4];
        float ox = (1.f / (1.f + expf(-(q01.x + b4.x)))) * rp[0];
        float oy = (1.f / (1.f + expf(-(q01.y + b4.y)))) * rp[1];
        float oz = (1.f / (1.f + expf(-(q23.x + b4.z)))) * rp[2];
        float ow = (1.f / (1.f + expf(-(q23.y + b4.w)))) * rp[3];
        __half2* yp = (__half2*)(Yt + qidx);
        yp[0] = __floats2half2_rn(ox, oy);
        yp[1] = __floats2half2_rn(oz, ow);
    }
}

// ===========================================================================
// Fused batch-max + exp + bias-fold over half K/V.
// 4 halves (8 B) per thread; hmax2 batch-max (exact on identical halves).
// ===========================================================================
__global__ __launch_bounds__(128)
void kmax_ekv_kernel(const __half* __restrict__ Kh, const __half* __restrict__ Vh,
                     const float* __restrict__ bv,
                     __half* __restrict__ EK, __half* __restrict__ EKV)
{
    const int idx = (blockIdx.x * 128 + threadIdx.x) * 4;   // < TT*DD
    const float4 bvv = __ldg((const float4*)(bv + (idx & (DD - 1))));

    uint2 kvh[BB];
    __half2 m0 = __float2half2_rn(-65504.f), m1 = m0;
#pragma unroll
    for (int b = 0; b < BB; b++) {
        kvh[b] = *(const uint2*)(Kh + (size_t)b * TT * DD + idx);
        m0 = __hmax2(m0, *(const __half2*)&kvh[b].x);
        m1 = __hmax2(m1, *(const __half2*)&kvh[b].y);
    }
    const float2 mf0 = __half22float2(m0);
    const float2 mf1 = __half22float2(m1);
#pragma unroll
    for (int b = 0; b < BB; b++) {
        const size_t gi = (size_t)b * TT * DD + idx;
        uint2 vv = *(const uint2*)(Vh + gi);
        float2 k0 = __half22float2(*(const __half2*)&kvh[b].x);
        float2 k1 = __half22float2(*(const __half2*)&kvh[b].y);
        float2 v0 = __half22float2(*(const __half2*)&vv.x);
        float2 v1 = __half22float2(*(const __half2*)&vv.y);
        const float e0 = expf(k0.x - mf0.x);
        const float e1 = expf(k0.y - mf0.y);
        const float e2 = expf(k1.x - mf1.x);
        const float e3 = expf(k1.y - mf1.y);
        uint2 ek, ekv;
        *(__half2*)&ek.x  = __floats2half2_rn(e0, e1);
        *(__half2*)&ek.y  = __floats2half2_rn(e2, e3);
        *(__half2*)&ekv.x = __floats2half2_rn(e0 * (v0.x + bvv.x), e1 * (v0.y + bvv.y));
        *(__half2*)&ekv.y = __floats2half2_rn(e2 * (v1.x + bvv.z), e3 * (v1.y + bvv.w));
        *(uint2*)(EK + gi)  = ek;
        *(uint2*)(EKV + gi) = ekv;
    }
}

// ===========================================================================
// Merged prep: f2h(x) [blocks 0..16383], wconv [16384..17407],
// brep [17408..17439], expw rows [17440..18463]
// ===========================================================================
__global__ __launch_bounds__(256)
void prep_kernel(const float* __restrict__ x, __half* __restrict__ xh,
                 const float* __restrict__ Wk, const float* __restrict__ Wv,
                 const float* __restrict__ Wq, const float* __restrict__ Wo,
                 __half* __restrict__ W3h, __half* __restrict__ Woh,
                 const float* __restrict__ bo, float* __restrict__ brep,
                 const float* __restrict__ w, __half* __restrict__ ew)
{
    const int blk = blockIdx.x;
    if (blk < 16384) {
        const size_t f = (size_t)blk * 256 + threadIdx.x;   // f4 index over x
        float4 v = ((const float4*)x)[f];
        __half2* d = (__half2*)(xh + f * 4);
        d[0] = __floats2half2_rn(v.x, v.y);
        d[1] = __floats2half2_rn(v.z, v.w);
    } else if (blk < 17408) {
        const int f = (blk - 16384) * 256 + threadIdx.x;    // f4 index < 4*65536
        const int per = DD * DD / 4;
        const float* src; __half* dst; int off;
        if (f < per)           { src = Wk; dst = W3h;            off = f; }
        else if (f < 2 * per)  { src = Wv; dst = W3h + DD * DD;  off = f - per; }
        else if (f < 3 * per)  { src = Wq; dst = W3h + 2*DD*DD;  off = f - 2 * per; }
        else                   { src = Wo; dst = Woh;            off = f - 3 * per; }
        float4 v = ((const float4*)src)[off];
        __half2* d = (__half2*)(dst + (size_t)off * 4);
        d[0] = __floats2half2_rn(v.x, v.y);
        d[1] = __floats2half2_rn(v.z, v.w);
    } else if (blk < 17440) {
        const int idx = (blk - 17408) * 256 + threadIdx.x;  // < 16*DD
        brep[idx] = bo[idx & (DD - 1)];
    } else {
        // exp_w row: per-row max then exp(w - max)
        const int t = blk - 17440;
        const float* row = w + (size_t)t * TT;
        float m = -INFINITY;
        for (int i = threadIdx.x; i < TT; i += 256) m = fmaxf(m, row[i]);
#pragma unroll
        for (int o = 16; o > 0; o >>= 1)
            m = fmaxf(m, __shfl_xor_sync(0xffffffffu, m, o));
        __shared__ float warpmax[8];
        __shared__ float rowmax;
        if ((threadIdx.x & 31) == 0) warpmax[threadIdx.x >> 5] = m;
        __syncthreads();
        if (threadIdx.x == 0) {
            float mm = warpmax[0];
#pragma unroll
            for (int i = 1; i < 8; i++) mm = fmaxf(mm, warpmax[i]);
            rowmax = mm;
        }
        __syncthreads();
        const float rm = rowmax;
        for (int i = threadIdx.x; i < TT; i += 256)
            ew[(size_t)t * TT + i] = __float2half(expf(row[i] - rm));
    }
}

// ===========================================================================
extern "C" void kernel_launch(void* const* d_in, const int* in_sizes, int n_in,
                              void* d_out, int out_size)
{
    const float* x    = (const float*)d_in[0];
    const float* Wk_w = (const float*)d_in[1];
    // Wk_b unused: K bias cancels inside exp(K - max_b K)
    const float* Wv_w = (const float*)d_in[3];
    const float* Wv_b = (const float*)d_in[4];
    const float* Wq_w = (const float*)d_in[5];
    const float* Wq_b = (const float*)d_in[6];
    const float* w    = (const float*)d_in[7];
    const float* Wo_w = (const float*)d_in[8];
    const float* Wo_b = (const float*)d_in[9];
    float* out = (float*)d_out;

    float *pbrep;
    __half *pKh, *pVh, *pQh, *pxh, *pW3h, *pWoh, *pexpwh, *pEKh, *pEKVh, *pYth;
    cudaGetSymbolAddress((void**)&pbrep, g_brep);
    cudaGetSymbolAddress((void**)&pKh, g_Kh);
    cudaGetSymbolAddress((void**)&pVh, g_Vh);
    cudaGetSymbolAddress((void**)&pQh, g_Qh);
    cudaGetSymbolAddress((void**)&pxh, g_xh);
    cudaGetSymbolAddress((void**)&pW3h, g_W3h);
    cudaGetSymbolAddress((void**)&pWoh, g_Woh);
    cudaGetSymbolAddress((void**)&pexpwh, g_expwh);
    cudaGetSymbolAddress((void**)&pEKh, g_EKh);
    cudaGetSymbolAddress((void**)&pEKVh, g_EKVh);
    cudaGetSymbolAddress((void**)&pYth, g_Yth);

    cudaFuncSetAttribute(linh,  cudaFuncAttributeMaxDynamicSharedMemorySize, L_SMEM);
    cudaFuncSetAttribute(attnh, cudaFuncAttributeMaxDynamicSharedMemorySize, A_SMEM);

    // #1 prep (f2h + wconv + brep + expw)
    prep_kernel<<<18464, 256>>>(x, pxh, Wk_w, Wv_w, Wq_w, Wo_w, pW3h, pWoh,
                                Wo_b, pbrep, w, pexpwh);

    // #2 fused K/V/Q linear (half out): N = 1536 -> grid (12, 256)
    linh<<<dim3(12, MM / 128), 128, L_SMEM>>>(pxh, pW3h, pbrep, pKh, pVh, pQh, nullptr);

    // #3 fused batch-max + exp (+ V bias)
    kmax_ekv_kernel<<<(TT * DD / 4) / 128, 128>>>(pKh, pVh, Wv_b, pEKh, pEKVh);

    // #4 attention (profiled next round)
    attnh<<<dim3(DD / 64, TT / 128, BB), 128, A_SMEM>>>(pexpwh, pEKh, pEKVh, pQh, Wq_b, pYth);

    // #5 final linear with bias (fp32 out): N = 512 -> grid (4, 256)
    linh<<<dim3(4, MM / 128), 128, L_SMEM>>>(pYth, pWoh, pbrep, nullptr, nullptr, nullptr, out);
}

// round 13
// speedup vs baseline: 1.1037x; 1.0781x over previous
#include <cuda_runtime.h>
#include <cuda_fp16.h>
#include <math.h>
#include <mma.h>
#include <stdint.h>

using namespace nvcuda;

#define BB 32
#define TT 1024
#define DD 512
#define MM (BB * TT)

// Scratch (__device__ globals; no allocations allowed)
__device__ float  g_brep[16 * DD];
__device__ __half g_Kh[MM * DD];
__device__ __half g_Vh[MM * DD];
__device__ __half g_Qh[MM * DD];
__device__ __half g_xh[MM * DD];
__device__ __half g_W3h[3 * DD * DD];
__device__ __half g_Woh[DD * DD];
__device__ __half g_expwh[TT * TT];
__device__ __half g_EKh[MM * DD];
__device__ __half g_EKVh[MM * DD];
__device__ __half g_Yth[MM * DD];

__device__ __forceinline__ uint32_t smem_u32(const void* p) {
    uint32_t a;
    asm("{ .reg .u64 t; cvta.to.shared.u64 t, %1; cvt.u32.u64 %0, t; }"
        : "=r"(a) : "l"(p));
    return a;
}

#define CP16(dst, src) \
    asm volatile("cp.async.cg.shared.global [%0], [%1], 16;" \
        :: "r"(smem_u32(dst)), "l"((const void*)(src)) : "memory")
#define CP_COMMIT() asm volatile("cp.async.commit_group;" ::: "memory")
#define CP_WAIT0()  asm volatile("cp.async.wait_group 0;" ::: "memory")

// ===========================================================================
// Linear NT GEMM (fp16 WMMA, fp32 acc, K-chunk 64, 2-stage double buffer)
// Block 128x128, 128 threads, 4 warps (2x2), warp tile 64x64.
// 3 CTAs/SM => 12 warps/SM. Stage = As 128x72 + Bs 128x72 = 36864 B.
// Fused mode (outf==null): convert acc to half, route to Kh/Vh/Qh by n>>9.
// ===========================================================================
#define L_STAGE 18432   // halves per stage
#define L_SMEM (2 * L_STAGE * 2)   // 73728 B

__global__ __launch_bounds__(128, 3)
void linh(const __half* __restrict__ A, const __half* __restrict__ W,
          const float* __restrict__ brep,
          __half* __restrict__ Kh, __half* __restrict__ Vh, __half* __restrict__ Qh,
          float* __restrict__ outf)
{
    extern __shared__ __half sh[];
    const int tid = threadIdx.x;
    const int wid = tid >> 5;
    const int wm = wid >> 1;          // 0..1 (64 rows)
    const int wn = wid & 1;           // 0..1 (64 cols)
    const int m0 = blockIdx.y * 128, n0 = blockIdx.x * 128;

    wmma::fragment<wmma::accumulator, 16, 16, 16, float> c[4][4];
#pragma unroll
    for (int i = 0; i < 4; i++)
#pragma unroll
        for (int j = 0; j < 4; j++) {
            if (outf)
                wmma::load_matrix_sync(c[i][j],
                    brep + ((n0 + wn * 64 + j * 16) & (DD - 1)),
                    DD, wmma::mem_row_major);
            else
                wmma::fill_fragment(c[i][j], 0.0f);
        }

    auto issue = [&](int chunk) {
        __half* As = sh + (chunk & 1) * L_STAGE;
        __half* Bs = As + 128 * 72;
        const int k0 = chunk * 64;
#pragma unroll
        for (int i = 0; i < 8; i++) {          // As: 128x64 -> 1024 cp16
            const int f = tid + i * 128;
            const int row = f >> 3, c8 = f & 7;
            CP16(As + row * 72 + c8 * 8, A + (size_t)(m0 + row) * DD + k0 + c8 * 8);
        }
#pragma unroll
        for (int i = 0; i < 8; i++) {          // Bs: 128x64 -> 1024 cp16
            const int f = tid + i * 128;
            const int row = f >> 3, c8 = f & 7;
            CP16(Bs + row * 72 + c8 * 8, W + (size_t)(n0 + row) * DD + k0 + c8 * 8);
        }
        CP_COMMIT();
    };

    issue(0);

    const int NC = DD / 64;   // 8
    for (int ch = 0; ch < NC; ch++) {
        CP_WAIT0();
        __syncthreads();
        if (ch + 1 < NC) issue(ch + 1);   // overlaps with compute(ch)

        const __half* As = sh + (ch & 1) * L_STAGE;
        const __half* Bs = As + 128 * 72;
#pragma unroll
        for (int kk = 0; kk < 4; kk++) {
            wmma::fragment<wmma::matrix_a, 16, 16, 16, __half, wmma::row_major> a[4];
            wmma::fragment<wmma::matrix_b, 16, 16, 16, __half, wmma::col_major> b[4];
#pragma unroll
            for (int i = 0; i < 4; i++)
                wmma::load_matrix_sync(a[i], As + (wm * 64 + i * 16) * 72 + kk * 16, 72);
#pragma unroll
            for (int j = 0; j < 4; j++)
                wmma::load_matrix_sync(b[j], Bs + (wn * 64 + j * 16) * 72 + kk * 16, 72);
#pragma unroll
            for (int i = 0; i < 4; i++)
#pragma unroll
                for (int j = 0; j < 4; j++)
                    wmma::mma_sync(c[i][j], a[i], b[j], c[i][j]);
        }
    }

    if (outf) {
#pragma unroll
        for (int i = 0; i < 4; i++)
#pragma unroll
            for (int j = 0; j < 4; j++)
                wmma::store_matrix_sync(outf + (size_t)(m0 + wm * 64 + i * 16) * DD
                                             + n0 + wn * 64 + j * 16,
                                        c[i][j], DD, wmma::mem_row_major);
    } else {
        const int mat = n0 >> 9;
        __half* dst = (mat == 0) ? Kh : (mat == 1) ? Vh : Qh;
        const int col0 = n0 & 511;
        wmma::fragment<wmma::accumulator, 16, 16, 16, __half> chf;
#pragma unroll
        for (int i = 0; i < 4; i++)
#pragma unroll
            for (int j = 0; j < 4; j++) {
#pragma unroll
                for (int e = 0; e < chf.num_elements; e++)
                    chf.x[e] = __float2half(c[i][j].x[e]);
                wmma::store_matrix_sync(dst + (size_t)(m0 + wm * 64 + i * 16) * DD
                                            + col0 + wn * 64 + j * 16,
                                        chf, DD, wmma::mem_row_major);
            }
    }
}

// ===========================================================================
// Attention (fp16 WMMA): num = expw @ EKV, den = expw @ EK per batch.
// K(s)-chunk 64, 2-stage double buffer. Division in registers; only ratio
// staged in smem. Block 128(t) x 64(d), 128 threads, warp 64t x 32d dual-acc.
// Stage = Ws 128x72 + EK 64x72 + EKV 64x72 = 36864 B. 3 CTAs/SM.
// ===========================================================================
#define A_STAGE 18432   // halves per stage
#define A_SMEM (2 * A_STAGE * 2)   // 73728 B (epi ratio: 128*68*4 = 34816)

__global__ __launch_bounds__(128, 3)
void attnh(const __half* __restrict__ expw, const __half* __restrict__ EK,
           const __half* __restrict__ EKV, const __half* __restrict__ Qh,
           const float* __restrict__ bq, __half* __restrict__ Yt)
{
    extern __shared__ __half sh[];
    const int tid = threadIdx.x;
    const int wid = tid >> 5;
    const int wm = wid >> 1;          // 0..1 (64 t-rows)
    const int wn = wid & 1;           // 0..1 (32 d-cols)
    const int d0 = blockIdx.x * 64, t0 = blockIdx.y * 128, b = blockIdx.z;

    const __half* ekb  = EK  + (size_t)b * TT * DD;
    const __half* ekvb = EKV + (size_t)b * TT * DD;

    wmma::fragment<wmma::accumulator, 16, 16, 16, float> cN[4][2], cD[4][2];
#pragma unroll
    for (int i = 0; i < 4; i++)
#pragma unroll
        for (int j = 0; j < 2; j++) {
            wmma::fill_fragment(cN[i][j], 0.0f);
            wmma::fill_fragment(cD[i][j], 0.0f);
        }

    auto issue = [&](int chunk) {
        __half* Ws  = sh + (chunk & 1) * A_STAGE;
        __half* EKs = Ws + 128 * 72;
        __half* EVs = EKs + 64 * 72;
        const int s0 = chunk * 64;
#pragma unroll
        for (int i = 0; i < 8; i++) {          // Ws: 128x64 -> 1024 cp16
            const int f = tid + i * 128;
            const int row = f >> 3, c8 = f & 7;
            CP16(Ws + row * 72 + c8 * 8, expw + (size_t)(t0 + row) * TT + s0 + c8 * 8);
        }
#pragma unroll
        for (int i = 0; i < 4; i++) {          // EK/EKV: 64x64 -> 512 cp16 each
            const int f = tid + i * 128;
            const int row = f >> 3, c8 = f & 7;
            CP16(EKs + row * 72 + c8 * 8, ekb  + (size_t)(s0 + row) * DD + d0 + c8 * 8);
            CP16(EVs + row * 72 + c8 * 8, ekvb + (size_t)(s0 + row) * DD + d0 + c8 * 8);
        }
        CP_COMMIT();
    };

    issue(0);

    const int NC = TT / 64;   // 16
    for (int ch = 0; ch < NC; ch++) {
        CP_WAIT0();
        __syncthreads();
        if (ch + 1 < NC) issue(ch + 1);   // overlaps with compute(ch)

        const __half* Ws  = sh + (ch & 1) * A_STAGE;
        const __half* EKs = Ws + 128 * 72;
        const __half* EVs = EKs + 64 * 72;
#pragma unroll
        for (int kk = 0; kk < 4; kk++) {
            wmma::fragment<wmma::matrix_a, 16, 16, 16, __half, wmma::row_major> a[4];
            wmma::fragment<wmma::matrix_b, 16, 16, 16, __half, wmma::row_major> bK[2], bV[2];
#pragma unroll
            for (int i = 0; i < 4; i++)
                wmma::load_matrix_sync(a[i], Ws + (wm * 64 + i * 16) * 72 + kk * 16, 72);
#pragma unroll
            for (int j = 0; j < 2; j++) {
                wmma::load_matrix_sync(bK[j], EKs + (kk * 16) * 72 + wn * 32 + j * 16, 72);
                wmma::load_matrix_sync(bV[j], EVs + (kk * 16) * 72 + wn * 32 + j * 16, 72);
            }
#pragma unroll
            for (int i = 0; i < 4; i++)
#pragma unroll
                for (int j = 0; j < 2; j++) {
                    wmma::mma_sync(cN[i][j], a[i], bV[j], cN[i][j]);
                    wmma::mma_sync(cD[i][j], a[i], bK[j], cD[i][j]);
                }
        }
    }

    __syncthreads();
    float* ratio = (float*)sh;           // [128][68]
#pragma unroll
    for (int i = 0; i < 4; i++)
#pragma unroll
        for (int j = 0; j < 2; j++) {
#pragma unroll
            for (int e = 0; e < cN[i][j].num_elements; e++)
                cN[i][j].x[e] /= cD[i][j].x[e];
            wmma::store_matrix_sync(&ratio[(wm * 64 + i * 16) * 68 + wn * 32 + j * 16],
                                    cN[i][j], 68, wmma::mem_row_major);
        }
    __syncthreads();

#pragma unroll
    for (int it = 0; it < 16; it++) {
        const int f = tid + it * 128;        // 0..2047 groups of 4 over 128x64
        const int row = f >> 4, c4 = f & 15;
        const size_t qidx = ((size_t)b * TT + t0 + row) * DD + d0 + c4 * 4;
        const __half2* qp = (const __half2*)(Qh + qidx);
        float2 q01 = __half22float2(qp[0]);
        float2 q23 = __half22float2(qp[1]);
        float4 b4 = __ldg((const float4*)(bq + d0 + c4 * 4));
        const float* rp = &ratio[row * 68 + c4 * 4];
        float ox = (1.f / (1.f + expf(-(q01.x + b4.x)))) * rp[0];
        float oy = (1.f / (1.f + expf(-(q01.y + b4.y)))) * rp[1];
        float oz = (1.f / (1.f + expf(-(q23.x + b4.z)))) * rp[2];
        float ow = (1.f / (1.f + expf(-(q23.y + b4.w)))) * rp[3];
        __half2* yp = (__half2*)(Yt + qidx);
        yp[0] = __floats2half2_rn(ox, oy);
        yp[1] = __floats2half2_rn(oz, ow);
    }
}

// ===========================================================================
// Fused batch-max + exp + bias-fold over half K/V (4 halves / thread)
// ===========================================================================
__global__ __launch_bounds__(128)
void kmax_ekv_kernel(const __half* __restrict__ Kh, const __half* __restrict__ Vh,
                     const float* __restrict__ bv,
                     __half* __restrict__ EK, __half* __restrict__ EKV)
{
    const int idx = (blockIdx.x * 128 + threadIdx.x) * 4;   // < TT*DD
    const float4 bvv = __ldg((const float4*)(bv + (idx & (DD - 1))));

    uint2 kvh[BB];
    __half2 m0 = __float2half2_rn(-65504.f), m1 = m0;
#pragma unroll
    for (int b = 0; b < BB; b++) {
        kvh[b] = *(const uint2*)(Kh + (size_t)b * TT * DD + idx);
        m0 = __hmax2(m0, *(const __half2*)&kvh[b].x);
        m1 = __hmax2(m1, *(const __half2*)&kvh[b].y);
    }
    const float2 mf0 = __half22float2(m0);
    const float2 mf1 = __half22float2(m1);
#pragma unroll
    for (int b = 0; b < BB; b++) {
        const size_t gi = (size_t)b * TT * DD + idx;
        uint2 vv = *(const uint2*)(Vh + gi);
        float2 k0 = __half22float2(*(const __half2*)&kvh[b].x);
        float2 k1 = __half22float2(*(const __half2*)&kvh[b].y);
        float2 v0 = __half22float2(*(const __half2*)&vv.x);
        float2 v1 = __half22float2(*(const __half2*)&vv.y);
        const float e0 = expf(k0.x - mf0.x);
        const float e1 = expf(k0.y - mf0.y);
        const float e2 = expf(k1.x - mf1.x);
        const float e3 = expf(k1.y - mf1.y);
        uint2 ek, ekv;
        *(__half2*)&ek.x  = __floats2half2_rn(e0, e1);
        *(__half2*)&ek.y  = __floats2half2_rn(e2, e3);
        *(__half2*)&ekv.x = __floats2half2_rn(e0 * (v0.x + bvv.x), e1 * (v0.y + bvv.y));
        *(__half2*)&ekv.y = __floats2half2_rn(e2 * (v1.x + bvv.z), e3 * (v1.y + bvv.w));
        *(uint2*)(EK + gi)  = ek;
        *(uint2*)(EKV + gi) = ekv;
    }
}

// ===========================================================================
// Merged prep: f2h(x) [blocks 0..16383], wconv [16384..17407],
// brep [17408..17439], expw rows [17440..18463]
// ===========================================================================
__global__ __launch_bounds__(256)
void prep_kernel(const float* __restrict__ x, __half* __restrict__ xh,
                 const float* __restrict__ Wk, const float* __restrict__ Wv,
                 const float* __restrict__ Wq, const float* __restrict__ Wo,
                 __half* __restrict__ W3h, __half* __restrict__ Woh,
                 const float* __restrict__ bo, float* __restrict__ brep,
                 const float* __restrict__ w, __half* __restrict__ ew)
{
    const int blk = blockIdx.x;
    if (blk < 16384) {
        const size_t f = (size_t)blk * 256 + threadIdx.x;   // f4 index over x
        float4 v = ((const float4*)x)[f];
        __half2* d = (__half2*)(xh + f * 4);
        d[0] = __floats2half2_rn(v.x, v.y);
        d[1] = __floats2half2_rn(v.z, v.w);
    } else if (blk < 17408) {
        const int f = (blk - 16384) * 256 + threadIdx.x;    // f4 index < 4*65536
        const int per = DD * DD / 4;
        const float* src; __half* dst; int off;
        if (f < per)           { src = Wk; dst = W3h;            off = f; }
        else if (f < 2 * per)  { src = Wv; dst = W3h + DD * DD;  off = f - per; }
        else if (f < 3 * per)  { src = Wq; dst = W3h + 2*DD*DD;  off = f - 2 * per; }
        else                   { src = Wo; dst = Woh;            off = f - 3 * per; }
        float4 v = ((const float4*)src)[off];
        __half2* d = (__half2*)(dst + (size_t)off * 4);
        d[0] = __floats2half2_rn(v.x, v.y);
        d[1] = __floats2half2_rn(v.z, v.w);
    } else if (blk < 17440) {
        const int idx = (blk - 17408) * 256 + threadIdx.x;  // < 16*DD
        brep[idx] = bo[idx & (DD - 1)];
    } else {
        const int t = blk - 17440;
        const float* row = w + (size_t)t * TT;
        float m = -INFINITY;
        for (int i = threadIdx.x; i < TT; i += 256) m = fmaxf(m, row[i]);
#pragma unroll
        for (int o = 16; o > 0; o >>= 1)
            m = fmaxf(m, __shfl_xor_sync(0xffffffffu, m, o));
        __shared__ float warpmax[8];
        __shared__ float rowmax;
        if ((threadIdx.x & 31) == 0) warpmax[threadIdx.x >> 5] = m;
        __syncthreads();
        if (threadIdx.x == 0) {
            float mm = warpmax[0];
#pragma unroll
            for (int i = 1; i < 8; i++) mm = fmaxf(mm, warpmax[i]);
            rowmax = mm;
        }
        __syncthreads();
        const float rm = rowmax;
        for (int i = threadIdx.x; i < TT; i += 256)
            ew[(size_t)t * TT + i] = __float2half(expf(row[i] - rm));
    }
}

// ===========================================================================
extern "C" void kernel_launch(void* const* d_in, const int* in_sizes, int n_in,
                              void* d_out, int out_size)
{
    const float* x    = (const float*)d_in[0];
    const float* Wk_w = (const float*)d_in[1];
    // Wk_b unused: K bias cancels inside exp(K - max_b K)
    const float* Wv_w = (const float*)d_in[3];
    const float* Wv_b = (const float*)d_in[4];
    const float* Wq_w = (const float*)d_in[5];
    const float* Wq_b = (const float*)d_in[6];
    const float* w    = (const float*)d_in[7];
    const float* Wo_w = (const float*)d_in[8];
    const float* Wo_b = (const float*)d_in[9];
    float* out = (float*)d_out;

    float *pbrep;
    __half *pKh, *pVh, *pQh, *pxh, *pW3h, *pWoh, *pexpwh, *pEKh, *pEKVh, *pYth;
    cudaGetSymbolAddress((void**)&pbrep, g_brep);
    cudaGetSymbolAddress((void**)&pKh, g_Kh);
    cudaGetSymbolAddress((void**)&pVh, g_Vh);
    cudaGetSymbolAddress((void**)&pQh, g_Qh);
    cudaGetSymbolAddress((void**)&pxh, g_xh);
    cudaGetSymbolAddress((void**)&pW3h, g_W3h);
    cudaGetSymbolAddress((void**)&pWoh, g_Woh);
    cudaGetSymbolAddress((void**)&pexpwh, g_expwh);
    cudaGetSymbolAddress((void**)&pEKh, g_EKh);
    cudaGetSymbolAddress((void**)&pEKVh, g_EKVh);
    cudaGetSymbolAddress((void**)&pYth, g_Yth);

    cudaFuncSetAttribute(linh,  cudaFuncAttributeMaxDynamicSharedMemorySize, L_SMEM);
    cudaFuncSetAttribute(attnh, cudaFuncAttributeMaxDynamicSharedMemorySize, A_SMEM);

    // #1 prep (f2h + wconv + brep + expw)
    prep_kernel<<<18464, 256>>>(x, pxh, Wk_w, Wv_w, Wq_w, Wo_w, pW3h, pWoh,
                                Wo_b, pbrep, w, pexpwh);

    // #2 fused K/V/Q linear (half out): N = 1536 -> grid (12, 256)
    linh<<<dim3(12, MM / 128), 128, L_SMEM>>>(pxh, pW3h, pbrep, pKh, pVh, pQh, nullptr);

    // #3 fused batch-max + exp (+ V bias)
    kmax_ekv_kernel<<<(TT * DD / 4) / 128, 128>>>(pKh, pVh, Wv_b, pEKh, pEKVh);

    // #4 attention
    attnh<<<dim3(DD / 64, TT / 128, BB), 128, A_SMEM>>>(pexpwh, pEKh, pEKVh, pQh, Wq_b, pYth);

    // #5 final linear with bias (fp32 out): N = 512 -> grid (4, 256)
    linh<<<dim3(4, MM / 128), 128, L_SMEM>>>(pYth, pWoh, pbrep, nullptr, nullptr, nullptr, out);
}

// round 14
// speedup vs baseline: 1.1329x; 1.0264x over previous
#include <cuda_runtime.h>
#include <cuda_fp16.h>
#include <math.h>
#include <mma.h>
#include <stdint.h>

using namespace nvcuda;

#define BB 32
#define TT 1024
#define DD 512
#define MM (BB * TT)

// Scratch (__device__ globals; no allocations allowed)
__device__ float  g_brep[16 * DD];        // replicated Wo bias (final linear)
__device__ float  g_brep3[16 * 3 * DD];   // replicated [0 | 0 | bq] (fused linear)
__device__ __half g_Kh[MM * DD];
__device__ __half g_Vh[MM * DD];
__device__ __half g_Qh[MM * DD];
__device__ __half g_xh[MM * DD];
__device__ __half g_W3h[3 * DD * DD];
__device__ __half g_Woh[DD * DD];
__device__ __half g_expwh[TT * TT];
__device__ __half g_EKh[MM * DD];
__device__ __half g_EKVh[MM * DD];
__device__ __half g_Yth[MM * DD];

__device__ __forceinline__ uint32_t smem_u32(const void* p) {
    uint32_t a;
    asm("{ .reg .u64 t; cvta.to.shared.u64 t, %1; cvt.u32.u64 %0, t; }"
        : "=r"(a) : "l"(p));
    return a;
}

#define CP16(dst, src) \
    asm volatile("cp.async.cg.shared.global [%0], [%1], 16;" \
        :: "r"(smem_u32(dst)), "l"((const void*)(src)) : "memory")
#define CP_COMMIT() asm volatile("cp.async.commit_group;" ::: "memory")
#define CP_WAIT0()  asm volatile("cp.async.wait_group 0;" ::: "memory")

// ===========================================================================
// Linear NT GEMM (fp16 WMMA, fp32 acc, K-chunk 64, 2-stage double buffer)
// Block 128x128, 128 threads, 4 warps (2x2), warp tile 64x64. 3 CTAs/SM.
// Accumulators init from a replicated-bias tile (bias_rep, ld = ldb).
// Fused mode (outf==null): convert acc to half, route to Kh/Vh/Qh by n>>9.
// ===========================================================================
#define L_STAGE 18432   // halves per stage: As 128x72 + Bs 128x72
#define L_SMEM (2 * L_STAGE * 2)   // 73728 B

__global__ __launch_bounds__(128, 3)
void linh(const __half* __restrict__ A, const __half* __restrict__ W,
          const float* __restrict__ bias_rep, int ldb,
          __half* __restrict__ Kh, __half* __restrict__ Vh, __half* __restrict__ Qh,
          float* __restrict__ outf)
{
    extern __shared__ __half sh[];
    const int tid = threadIdx.x;
    const int wid = tid >> 5;
    const int wm = wid >> 1;          // 0..1 (64 rows)
    const int wn = wid & 1;           // 0..1 (64 cols)
    const int m0 = blockIdx.y * 128, n0 = blockIdx.x * 128;

    wmma::fragment<wmma::accumulator, 16, 16, 16, float> c[4][4];
#pragma unroll
    for (int i = 0; i < 4; i++)
#pragma unroll
        for (int j = 0; j < 4; j++)
            wmma::load_matrix_sync(c[i][j],
                bias_rep + n0 + wn * 64 + j * 16, ldb, wmma::mem_row_major);

    auto issue = [&](int chunk) {
        __half* As = sh + (chunk & 1) * L_STAGE;
        __half* Bs = As + 128 * 72;
        const int k0 = chunk * 64;
#pragma unroll
        for (int i = 0; i < 8; i++) {
            const int f = tid + i * 128;
            const int row = f >> 3, c8 = f & 7;
            CP16(As + row * 72 + c8 * 8, A + (size_t)(m0 + row) * DD + k0 + c8 * 8);
        }
#pragma unroll
        for (int i = 0; i < 8; i++) {
            const int f = tid + i * 128;
            const int row = f >> 3, c8 = f & 7;
            CP16(Bs + row * 72 + c8 * 8, W + (size_t)(n0 + row) * DD + k0 + c8 * 8);
        }
        CP_COMMIT();
    };

    issue(0);

    const int NC = DD / 64;   // 8
    for (int ch = 0; ch < NC; ch++) {
        CP_WAIT0();
        __syncthreads();
        if (ch + 1 < NC) issue(ch + 1);   // overlaps with compute(ch)

        const __half* As = sh + (ch & 1) * L_STAGE;
        const __half* Bs = As + 128 * 72;
#pragma unroll
        for (int kk = 0; kk < 4; kk++) {
            wmma::fragment<wmma::matrix_a, 16, 16, 16, __half, wmma::row_major> a[4];
            wmma::fragment<wmma::matrix_b, 16, 16, 16, __half, wmma::col_major> b[4];
#pragma unroll
            for (int i = 0; i < 4; i++)
                wmma::load_matrix_sync(a[i], As + (wm * 64 + i * 16) * 72 + kk * 16, 72);
#pragma unroll
            for (int j = 0; j < 4; j++)
                wmma::load_matrix_sync(b[j], Bs + (wn * 64 + j * 16) * 72 + kk * 16, 72);
#pragma unroll
            for (int i = 0; i < 4; i++)
#pragma unroll
                for (int j = 0; j < 4; j++)
                    wmma::mma_sync(c[i][j], a[i], b[j], c[i][j]);
        }
    }

    if (outf) {
#pragma unroll
        for (int i = 0; i < 4; i++)
#pragma unroll
            for (int j = 0; j < 4; j++)
                wmma::store_matrix_sync(outf + (size_t)(m0 + wm * 64 + i * 16) * DD
                                             + n0 + wn * 64 + j * 16,
                                        c[i][j], DD, wmma::mem_row_major);
    } else {
        const int mat = n0 >> 9;
        __half* dst = (mat == 0) ? Kh : (mat == 1) ? Vh : Qh;
        const int col0 = n0 & 511;
        wmma::fragment<wmma::accumulator, 16, 16, 16, __half> chf;
#pragma unroll
        for (int i = 0; i < 4; i++)
#pragma unroll
            for (int j = 0; j < 4; j++) {
#pragma unroll
                for (int e = 0; e < chf.num_elements; e++)
                    chf.x[e] = __float2half(c[i][j].x[e]);
                wmma::store_matrix_sync(dst + (size_t)(m0 + wm * 64 + i * 16) * DD
                                            + col0 + wn * 64 + j * 16,
                                        chf, DD, wmma::mem_row_major);
            }
    }
}

// ===========================================================================
// Attention (fp16 WMMA): num = expw @ EKV, den = expw @ EK per batch.
// K(s)-chunk 64, 2-stage double buffer. Fully-fragment epilogue:
// Yt = half( sigmoid(Qh) * cN/cD )   (bq pre-folded into Qh by linh).
// Block 128(t) x 64(d), 128 threads, warp 64t x 32d dual-acc. 3 CTAs/SM.
// ===========================================================================
#define A_STAGE 18432   // halves per stage: Ws 128x72 + EK 64x72 + EKV 64x72
#define A_SMEM (2 * A_STAGE * 2)   // 73728 B

__global__ __launch_bounds__(128, 3)
void attnh(const __half* __restrict__ expw, const __half* __restrict__ EK,
           const __half* __restrict__ EKV, const __half* __restrict__ Qh,
           __half* __restrict__ Yt)
{
    extern __shared__ __half sh[];
    const int tid = threadIdx.x;
    const int wid = tid >> 5;
    const int wm = wid >> 1;          // 0..1 (64 t-rows)
    const int wn = wid & 1;           // 0..1 (32 d-cols)
    const int d0 = blockIdx.x * 64, t0 = blockIdx.y * 128, b = blockIdx.z;

    const __half* ekb  = EK  + (size_t)b * TT * DD;
    const __half* ekvb = EKV + (size_t)b * TT * DD;

    wmma::fragment<wmma::accumulator, 16, 16, 16, float> cN[4][2], cD[4][2];
#pragma unroll
    for (int i = 0; i < 4; i++)
#pragma unroll
        for (int j = 0; j < 2; j++) {
            wmma::fill_fragment(cN[i][j], 0.0f);
            wmma::fill_fragment(cD[i][j], 0.0f);
        }

    auto issue = [&](int chunk) {
        __half* Ws  = sh + (chunk & 1) * A_STAGE;
        __half* EKs = Ws + 128 * 72;
        __half* EVs = EKs + 64 * 72;
        const int s0 = chunk * 64;
#pragma unroll
        for (int i = 0; i < 8; i++) {          // Ws: 128x64 -> 1024 cp16
            const int f = tid + i * 128;
            const int row = f >> 3, c8 = f & 7;
            CP16(Ws + row * 72 + c8 * 8, expw + (size_t)(t0 + row) * TT + s0 + c8 * 8);
        }
#pragma unroll
        for (int i = 0; i < 4; i++) {          // EK/EKV: 64x64 -> 512 cp16 each
            const int f = tid + i * 128;
            const int row = f >> 3, c8 = f & 7;
            CP16(EKs + row * 72 + c8 * 8, ekb  + (size_t)(s0 + row) * DD + d0 + c8 * 8);
            CP16(EVs + row * 72 + c8 * 8, ekvb + (size_t)(s0 + row) * DD + d0 + c8 * 8);
        }
        CP_COMMIT();
    };

    issue(0);

    const int NC = TT / 64;   // 16
    for (int ch = 0; ch < NC; ch++) {
        CP_WAIT0();
        __syncthreads();
        if (ch + 1 < NC) issue(ch + 1);   // overlaps with compute(ch)

        const __half* Ws  = sh + (ch & 1) * A_STAGE;
        const __half* EKs = Ws + 128 * 72;
        const __half* EVs = EKs + 64 * 72;
#pragma unroll
        for (int kk = 0; kk < 4; kk++) {
            wmma::fragment<wmma::matrix_a, 16, 16, 16, __half, wmma::row_major> a[4];
            wmma::fragment<wmma::matrix_b, 16, 16, 16, __half, wmma::row_major> bK[2], bV[2];
#pragma unroll
            for (int i = 0; i < 4; i++)
                wmma::load_matrix_sync(a[i], Ws + (wm * 64 + i * 16) * 72 + kk * 16, 72);
#pragma unroll
            for (int j = 0; j < 2; j++) {
                wmma::load_matrix_sync(bK[j], EKs + (kk * 16) * 72 + wn * 32 + j * 16, 72);
                wmma::load_matrix_sync(bV[j], EVs + (kk * 16) * 72 + wn * 32 + j * 16, 72);
            }
#pragma unroll
            for (int i = 0; i < 4; i++)
#pragma unroll
                for (int j = 0; j < 2; j++) {
                    wmma::mma_sync(cN[i][j], a[i], bV[j], cN[i][j]);
                    wmma::mma_sync(cD[i][j], a[i], bK[j], cD[i][j]);
                }
        }
    }

    // Fully-fragment epilogue: no smem staging, no extra syncs.
    // Element ordering of half-acc vs float-acc fragments matches (relied on
    // and validated by linh's fused epilogue since R8).
    wmma::fragment<wmma::accumulator, 16, 16, 16, __half> qf, yf;
#pragma unroll
    for (int i = 0; i < 4; i++)
#pragma unroll
        for (int j = 0; j < 2; j++) {
            const size_t tp = ((size_t)b * TT + t0 + wm * 64 + i * 16) * DD
                            + d0 + wn * 32 + j * 16;
            wmma::load_matrix_sync(qf, Qh + tp, DD, wmma::mem_row_major);
#pragma unroll
            for (int e = 0; e < qf.num_elements; e++) {
                const float q = __half2float(qf.x[e]);
                const float r = cN[i][j].x[e] / cD[i][j].x[e];
                yf.x[e] = __float2half((1.f / (1.f + expf(-q))) * r);
            }
            wmma::store_matrix_sync(Yt + tp, yf, DD, wmma::mem_row_major);
        }
}

// ===========================================================================
// Fused batch-max + exp + bias-fold over half K/V (4 halves / thread)
// ===========================================================================
__global__ __launch_bounds__(128)
void kmax_ekv_kernel(const __half* __restrict__ Kh, const __half* __restrict__ Vh,
                     const float* __restrict__ bv,
                     __half* __restrict__ EK, __half* __restrict__ EKV)
{
    const int idx = (blockIdx.x * 128 + threadIdx.x) * 4;   // < TT*DD
    const float4 bvv = __ldg((const float4*)(bv + (idx & (DD - 1))));

    uint2 kvh[BB];
    __half2 m0 = __float2half2_rn(-65504.f), m1 = m0;
#pragma unroll
    for (int b = 0; b < BB; b++) {
        kvh[b] = *(const uint2*)(Kh + (size_t)b * TT * DD + idx);
        m0 = __hmax2(m0, *(const __half2*)&kvh[b].x);
        m1 = __hmax2(m1, *(const __half2*)&kvh[b].y);
    }
    const float2 mf0 = __half22float2(m0);
    const float2 mf1 = __half22float2(m1);
#pragma unroll
    for (int b = 0; b < BB; b++) {
        const size_t gi = (size_t)b * TT * DD + idx;
        uint2 vv = *(const uint2*)(Vh + gi);
        float2 k0 = __half22float2(*(const __half2*)&kvh[b].x);
        float2 k1 = __half22float2(*(const __half2*)&kvh[b].y);
        float2 v0 = __half22float2(*(const __half2*)&vv.x);
        float2 v1 = __half22float2(*(const __half2*)&vv.y);
        const float e0 = expf(k0.x - mf0.x);
        const float e1 = expf(k0.y - mf0.y);
        const float e2 = expf(k1.x - mf1.x);
        const float e3 = expf(k1.y - mf1.y);
        uint2 ek, ekv;
        *(__half2*)&ek.x  = __floats2half2_rn(e0, e1);
        *(__half2*)&ek.y  = __floats2half2_rn(e2, e3);
        *(__half2*)&ekv.x = __floats2half2_rn(e0 * (v0.x + bvv.x), e1 * (v0.y + bvv.y));
        *(__half2*)&ekv.y = __floats2half2_rn(e2 * (v1.x + bvv.z), e3 * (v1.y + bvv.w));
        *(uint2*)(EK + gi)  = ek;
        *(uint2*)(EKV + gi) = ekv;
    }
}

// ===========================================================================
// Merged prep: f2h(x) [blocks 0..16383], wconv [16384..17407],
// brep+brep3 [17408..17503], expw rows [17504..18527]
// ===========================================================================
__global__ __launch_bounds__(256)
void prep_kernel(const float* __restrict__ x, __half* __restrict__ xh,
                 const float* __restrict__ Wk, const float* __restrict__ Wv,
                 const float* __restrict__ Wq, const float* __restrict__ Wo,
                 __half* __restrict__ W3h, __half* __restrict__ Woh,
                 const float* __restrict__ bo, float* __restrict__ brep,
                 const float* __restrict__ bq, float* __restrict__ brep3,
                 const float* __restrict__ w, __half* __restrict__ ew)
{
    const int blk = blockIdx.x;
    if (blk < 16384) {
        const size_t f = (size_t)blk * 256 + threadIdx.x;   // f4 index over x
        float4 v = ((const float4*)x)[f];
        __half2* d = (__half2*)(xh + f * 4);
        d[0] = __floats2half2_rn(v.x, v.y);
        d[1] = __floats2half2_rn(v.z, v.w);
    } else if (blk < 17408) {
        const int f = (blk - 16384) * 256 + threadIdx.x;    // f4 index < 4*65536
        const int per = DD * DD / 4;
        const float* src; __half* dst; int off;
        if (f < per)           { src = Wk; dst = W3h;            off = f; }
        else if (f < 2 * per)  { src = Wv; dst = W3h + DD * DD;  off = f - per; }
        else if (f < 3 * per)  { src = Wq; dst = W3h + 2*DD*DD;  off = f - 2 * per; }
        else                   { src = Wo; dst = Woh;            off = f - 3 * per; }
        float4 v = ((const float4*)src)[off];
        __half2* d = (__half2*)(dst + (size_t)off * 4);
        d[0] = __floats2half2_rn(v.x, v.y);
        d[1] = __floats2half2_rn(v.z, v.w);
    } else if (blk < 17440) {
        const int idx = (blk - 17408) * 256 + threadIdx.x;  // < 16*DD
        brep[idx] = bo[idx & (DD - 1)];
    } else if (blk < 17536) {
        const int idx = (blk - 17440) * 256 + threadIdx.x;  // < 16*1536
        const int col = idx % (3 * DD);
        brep3[idx] = (col >= 2 * DD) ? bq[col - 2 * DD] : 0.0f;
    } else {
        const int t = blk - 17536;
        const float* row = w + (size_t)t * TT;
        float m = -INFINITY;
        for (int i = threadIdx.x; i < TT; i += 256) m = fmaxf(m, row[i]);
#pragma unroll
        for (int o = 16; o > 0; o >>= 1)
            m = fmaxf(m, __shfl_xor_sync(0xffffffffu, m, o));
        __shared__ float warpmax[8];
        __shared__ float rowmax;
        if ((threadIdx.x & 31) == 0) warpmax[threadIdx.x >> 5] = m;
        __syncthreads();
        if (threadIdx.x == 0) {
            float mm = warpmax[0];
#pragma unroll
            for (int i = 1; i < 8; i++) mm = fmaxf(mm, warpmax[i]);
            rowmax = mm;
        }
        __syncthreads();
        const float rm = rowmax;
        for (int i = threadIdx.x; i < TT; i += 256)
            ew[(size_t)t * TT + i] = __float2half(expf(row[i] - rm));
    }
}

// ===========================================================================
extern "C" void kernel_launch(void* const* d_in, const int* in_sizes, int n_in,
                              void* d_out, int out_size)
{
    const float* x    = (const float*)d_in[0];
    const float* Wk_w = (const float*)d_in[1];
    // Wk_b unused: K bias cancels inside exp(K - max_b K)
    const float* Wv_w = (const float*)d_in[3];
    const float* Wv_b = (const float*)d_in[4];
    const float* Wq_w = (const float*)d_in[5];
    const float* Wq_b = (const float*)d_in[6];
    const float* w    = (const float*)d_in[7];
    const float* Wo_w = (const float*)d_in[8];
    const float* Wo_b = (const float*)d_in[9];
    float* out = (float*)d_out;

    float *pbrep, *pbrep3;
    __half *pKh, *pVh, *pQh, *pxh, *pW3h, *pWoh, *pexpwh, *pEKh, *pEKVh, *pYth;
    cudaGetSymbolAddress((void**)&pbrep, g_brep);
    cudaGetSymbolAddress((void**)&pbrep3, g_brep3);
    cudaGetSymbolAddress((void**)&pKh, g_Kh);
    cudaGetSymbolAddress((void**)&pVh, g_Vh);
    cudaGetSymbolAddress((void**)&pQh, g_Qh);
    cudaGetSymbolAddress((void**)&pxh, g_xh);
    cudaGetSymbolAddress((void**)&pW3h, g_W3h);
    cudaGetSymbolAddress((void**)&pWoh, g_Woh);
    cudaGetSymbolAddress((void**)&pexpwh, g_expwh);
    cudaGetSymbolAddress((void**)&pEKh, g_EKh);
    cudaGetSymbolAddress((void**)&pEKVh, g_EKVh);
    cudaGetSymbolAddress((void**)&pYth, g_Yth);

    cudaFuncSetAttribute(linh,  cudaFuncAttributeMaxDynamicSharedMemorySize, L_SMEM);
    cudaFuncSetAttribute(attnh, cudaFuncAttributeMaxDynamicSharedMemorySize, A_SMEM);

    // #1 prep (f2h + wconv + brep/brep3 + expw)
    prep_kernel<<<18560, 256>>>(x, pxh, Wk_w, Wv_w, Wq_w, Wo_w, pW3h, pWoh,
                                Wo_b, pbrep, Wq_b, pbrep3, w, pexpwh);

    // #2 fused K/V/Q linear (half out, bq folded into Q): N = 1536
    linh<<<dim3(12, MM / 128), 128, L_SMEM>>>(pxh, pW3h, pbrep3, 3 * DD,
                                              pKh, pVh, pQh, nullptr);

    // #3 fused batch-max + exp (+ V bias)
    kmax_ekv_kernel<<<(TT * DD / 4) / 128, 128>>>(pKh, pVh, Wv_b, pEKh, pEKVh);

    // #4 attention (fragment epilogue)
    attnh<<<dim3(DD / 64, TT / 128, BB), 128, A_SMEM>>>(pexpwh, pEKh, pEKVh, pQh, pYth);

    // #5 final linear with Wo bias (fp32 out): N = 512
    linh<<<dim3(4, MM / 128), 128, L_SMEM>>>(pYth, pWoh, pbrep, DD,
                                             nullptr, nullptr, nullptr, out);
}